// round 1
// baseline (speedup 1.0000x reference)
#include <cuda_runtime.h>

// Problem constants
#define NH    5
#define LD    10
#define PROJ  50           // NH*LD
#define C_DIM 256
#define B_DIM 32
#define HW    4096
#define M_ROWS (B_DIM * C_DIM)   // 8192
#define BN_EPS 1e-5f

// Scratch (device globals: no allocations allowed)
__device__ float g_P[3][M_ROWS * PROJ];   // q/k/v projections, [8192][50]
__device__ float g_Va[M_ROWS * PROJ];     // attention output in [b,c,nh*ld] layout
__device__ float g_scale[C_DIM];
__device__ float g_shift[C_DIM];

// ---------------------------------------------------------------------------
// K1: projection GEMMs.  P_z[M=8192, N=50] = A_z[8192, 4096] @ W_z[4096, 50]
// blockIdx.z selects (q,w_q), (k,w_k), (v,w_v).
// Tiling: BM=64, BN=64 (N padded 50->64), BK=16, 256 threads, 4x4 per thread.
// ---------------------------------------------------------------------------
__global__ __launch_bounds__(256) void k_proj(
    const float* __restrict__ q, const float* __restrict__ k,
    const float* __restrict__ v,
    const float* __restrict__ wq, const float* __restrict__ wk,
    const float* __restrict__ wv)
{
    const int z = blockIdx.z;
    const float* __restrict__ A = (z == 0) ? q : (z == 1) ? k : v;
    const float* __restrict__ W = (z == 0) ? wq : (z == 1) ? wk : wv;
    float* __restrict__ P = g_P[z];

    __shared__ float As[16][68];   // [k][m], padded to 68 (16B-aligned rows, conflict relief)
    __shared__ float Ws[16][64];   // [k][n]

    const int tid = threadIdx.x;
    const int tx = tid & 15;       // col group
    const int ty = tid >> 4;       // row group
    const int m0 = blockIdx.x * 64;

    // A-tile load mapping: one float4 of K per thread
    const int lm = tid >> 2;          // 0..63 (row within tile)
    const int lk = (tid & 3) * 4;     // 0,4,8,12 (k within tile)
    // W-tile load mapping: 4 scalar n's per thread
    const int wrow = tid >> 4;        // 0..15 (k within tile)
    const int wn   = (tid & 15) * 4;  // 0..60

    float acc[4][4];
#pragma unroll
    for (int i = 0; i < 4; i++)
#pragma unroll
        for (int j = 0; j < 4; j++) acc[i][j] = 0.f;

    const size_t arow = (size_t)(m0 + lm) * HW;

    for (int k0 = 0; k0 < HW; k0 += 16) {
        float4 a4 = *(const float4*)&A[arow + k0 + lk];
        As[lk + 0][lm] = a4.x;
        As[lk + 1][lm] = a4.y;
        As[lk + 2][lm] = a4.z;
        As[lk + 3][lm] = a4.w;
#pragma unroll
        for (int i = 0; i < 4; i++) {
            int n = wn + i;
            Ws[wrow][n] = (n < PROJ) ? W[(k0 + wrow) * PROJ + n] : 0.f;
        }
        __syncthreads();
#pragma unroll
        for (int kk = 0; kk < 16; kk++) {
            float4 a = *(const float4*)&As[kk][ty * 4];
            float4 w = *(const float4*)&Ws[kk][tx * 4];
            float ar[4] = {a.x, a.y, a.z, a.w};
            float wr[4] = {w.x, w.y, w.z, w.w};
#pragma unroll
            for (int i = 0; i < 4; i++)
#pragma unroll
                for (int j = 0; j < 4; j++)
                    acc[i][j] = fmaf(ar[i], wr[j], acc[i][j]);
        }
        __syncthreads();
    }

#pragma unroll
    for (int i = 0; i < 4; i++) {
        int row = m0 + ty * 4 + i;
#pragma unroll
        for (int j = 0; j < 4; j++) {
            int n = tx * 4 + j;
            if (n < PROJ) P[row * PROJ + n] = acc[i][j];
        }
    }
}

// ---------------------------------------------------------------------------
// K2: attention (tiny).  One block per batch, one thread per channel.
// S[i][j] = sum_{c,l} Pq[b,c,i*LD+l] * Pk[b,c,j*LD+l]
// attn = softmax(S / sqrt(feat)),  Va = Pv + attn applied over heads.
// Deterministic reduction (no atomics): warp shuffle -> per-warp slots -> fixed-order sum.
// ---------------------------------------------------------------------------
__global__ __launch_bounds__(256) void k_attn()
{
    const int b = blockIdx.x;
    const int c = threadIdx.x;            // 256 threads == 256 channels
    const int lane = c & 31;
    const int wid  = c >> 5;              // 8 warps

    const float* __restrict__ pq = &g_P[0][(b * C_DIM + c) * PROJ];
    const float* __restrict__ pk = &g_P[1][(b * C_DIM + c) * PROJ];
    const float* __restrict__ pv = &g_P[2][(b * C_DIM + c) * PROJ];

    float s[NH * NH];
#pragma unroll
    for (int i = 0; i < NH; i++) {
#pragma unroll
        for (int j = 0; j < NH; j++) {
            float a = 0.f;
#pragma unroll
            for (int l = 0; l < LD; l++)
                a = fmaf(pq[i * LD + l], pk[j * LD + l], a);
            s[i * NH + j] = a;
        }
    }

    __shared__ float sW[8][NH * NH];
    __shared__ float sA[NH * NH];

#pragma unroll
    for (int t = 0; t < NH * NH; t++) {
        float x = s[t];
#pragma unroll
        for (int off = 16; off > 0; off >>= 1)
            x += __shfl_down_sync(0xffffffffu, x, off);
        if (lane == 0) sW[wid][t] = x;
    }
    __syncthreads();

    if (c < NH) {  // thread i handles softmax row i
        const int i = c;
        const float inv_scale = rsqrtf((float)(C_DIM * LD));  // 1/sqrt(2560)
        float row[NH];
        float mx = -1e30f;
#pragma unroll
        for (int j = 0; j < NH; j++) {
            float acc = 0.f;
#pragma unroll
            for (int w = 0; w < 8; w++) acc += sW[w][i * NH + j];
            row[j] = acc * inv_scale;
            mx = fmaxf(mx, row[j]);
        }
        float sum = 0.f;
#pragma unroll
        for (int j = 0; j < NH; j++) { row[j] = expf(row[j] - mx); sum += row[j]; }
        float inv = 1.f / sum;
#pragma unroll
        for (int j = 0; j < NH; j++) sA[i * NH + j] = row[j] * inv;
    }
    __syncthreads();

    float* __restrict__ va = &g_Va[(b * C_DIM + c) * PROJ];
#pragma unroll
    for (int n = 0; n < NH; n++) {
#pragma unroll
        for (int l = 0; l < LD; l++) {
            float acc = pv[n * LD + l];   // residual inside attention
#pragma unroll
            for (int j = 0; j < NH; j++)
                acc = fmaf(sA[n * NH + j], pv[j * LD + l], acc);
            va[n * LD + l] = acc;
        }
    }
}

// ---------------------------------------------------------------------------
// K3: output GEMM + residual.  raw[8192, 4096] = vf + Va[8192,50] @ w_fc[50,4096]
// BM=64, BN=64, K=50 in one shot. 256 threads, 4x4 per thread.
// ---------------------------------------------------------------------------
__global__ __launch_bounds__(256) void k_out(
    const float* __restrict__ v, const float* __restrict__ wfc,
    float* __restrict__ out)
{
    __shared__ float Vas[PROJ][68];  // [k][row]
    __shared__ float Ws[PROJ][68];   // [k][col]

    const int tid = threadIdx.x;
    const int tx = tid & 15;
    const int ty = tid >> 4;
    const int n0 = blockIdx.x * 64;
    const int m0 = blockIdx.y * 64;

    for (int idx = tid; idx < PROJ * 64; idx += 256) {
        int kk = idx >> 6;        // 0..49
        int rr = idx & 63;
        Vas[kk][rr] = g_Va[(m0 + rr) * PROJ + kk];
        Ws[kk][rr]  = wfc[kk * HW + n0 + rr];
    }
    __syncthreads();

    float acc[4][4];
#pragma unroll
    for (int i = 0; i < 4; i++)
#pragma unroll
        for (int j = 0; j < 4; j++) acc[i][j] = 0.f;

#pragma unroll 10
    for (int kk = 0; kk < PROJ; kk++) {
        float4 a = *(const float4*)&Vas[kk][ty * 4];
        float4 w = *(const float4*)&Ws[kk][tx * 4];
        float ar[4] = {a.x, a.y, a.z, a.w};
        float wr[4] = {w.x, w.y, w.z, w.w};
#pragma unroll
        for (int i = 0; i < 4; i++)
#pragma unroll
            for (int j = 0; j < 4; j++)
                acc[i][j] = fmaf(ar[i], wr[j], acc[i][j]);
    }

#pragma unroll
    for (int i = 0; i < 4; i++) {
        const size_t row = (size_t)(m0 + ty * 4 + i) * HW + n0 + tx * 4;
        float4 vv = *(const float4*)&v[row];
        float4 o;
        o.x = vv.x + acc[i][0];
        o.y = vv.y + acc[i][1];
        o.z = vv.z + acc[i][2];
        o.w = vv.w + acc[i][3];
        *(float4*)&out[row] = o;
    }
}

// ---------------------------------------------------------------------------
// K4: per-channel batch stats over raw output -> scale/shift. One block/channel.
// ---------------------------------------------------------------------------
__global__ __launch_bounds__(256) void k_stats(
    const float* __restrict__ raw, const float* __restrict__ gamma,
    const float* __restrict__ beta)
{
    const int c = blockIdx.x;
    const int tid = threadIdx.x;
    float s = 0.f, s2 = 0.f;

    for (int b = 0; b < B_DIM; b++) {
        const float4* __restrict__ p =
            (const float4*)&raw[((size_t)b * C_DIM + c) * HW];
#pragma unroll
        for (int it = 0; it < HW / 4 / 256; it++) {
            float4 x = p[tid + it * 256];
            s  += x.x + x.y + x.z + x.w;
            s2 += x.x * x.x + x.y * x.y + x.z * x.z + x.w * x.w;
        }
    }

    __shared__ float rs[256], rs2[256];
    rs[tid] = s; rs2[tid] = s2;
    __syncthreads();
    for (int off = 128; off > 0; off >>= 1) {
        if (tid < off) { rs[tid] += rs[tid + off]; rs2[tid] += rs2[tid + off]; }
        __syncthreads();
    }
    if (tid == 0) {
        const float inv_n = 1.f / (float)(B_DIM * HW);  // 1/131072
        float mean = rs[0] * inv_n;
        float var  = rs2[0] * inv_n - mean * mean;
        float sc = gamma[c] * rsqrtf(var + BN_EPS);
        g_scale[c] = sc;
        g_shift[c] = beta[c] - mean * sc;
    }
}

// ---------------------------------------------------------------------------
// K5: apply BN affine in place.
// ---------------------------------------------------------------------------
__global__ __launch_bounds__(256) void k_apply(float* __restrict__ out)
{
    float4* __restrict__ p = (float4*)out;
    const int idx = blockIdx.x * 256 + threadIdx.x;   // 8192*256 = 2,097,152 threads
#pragma unroll
    for (int t = 0; t < 4; t++) {
        int i = idx + t * (8192 * 256);               // total 8,388,608 float4
        int c = (i >> 10) & 255;                      // (i*4/4096) % 256
        float sc = g_scale[c], sh = g_shift[c];
        float4 x = p[i];
        x.x = fmaf(x.x, sc, sh);
        x.y = fmaf(x.y, sc, sh);
        x.z = fmaf(x.z, sc, sh);
        x.w = fmaf(x.w, sc, sh);
        p[i] = x;
    }
}

// ---------------------------------------------------------------------------
extern "C" void kernel_launch(void* const* d_in, const int* in_sizes, int n_in,
                              void* d_out, int out_size)
{
    (void)in_sizes; (void)n_in; (void)out_size;
    const float* q     = (const float*)d_in[0];
    const float* k     = (const float*)d_in[1];
    const float* v     = (const float*)d_in[2];
    const float* wq    = (const float*)d_in[3];
    const float* wk    = (const float*)d_in[4];
    const float* wv    = (const float*)d_in[5];
    const float* wfc   = (const float*)d_in[6];
    const float* gamma = (const float*)d_in[7];
    const float* beta  = (const float*)d_in[8];
    float* out = (float*)d_out;

    k_proj<<<dim3(M_ROWS / 64, 1, 3), 256>>>(q, k, v, wq, wk, wv);
    k_attn<<<B_DIM, 256>>>();
    k_out<<<dim3(HW / 64, M_ROWS / 64), 256>>>(v, wfc, out);
    k_stats<<<C_DIM, 256>>>(out, gamma, beta);
    k_apply<<<8192, 256>>>(out);
}

// round 4
// speedup vs baseline: 1.6739x; 1.6739x over previous
#include <cuda_runtime.h>

// Problem constants
#define NH    5
#define LD    10
#define PROJ  50           // NH*LD
#define C_DIM 256
#define B_DIM 32
#define HW    4096
#define M_ROWS (B_DIM * C_DIM)   // 8192
#define BN_EPS 1e-5f

// Scratch (device globals: no allocations allowed)
__device__ float g_P[3][M_ROWS * PROJ];   // q/k/v projections, [8192][50]
__device__ float g_Va[M_ROWS * PROJ];     // attention output, [b*c][nh*ld]
__device__ float g_scale[C_DIM];
__device__ float g_shift[C_DIM];
__device__ float g_psum[4][C_DIM];
__device__ float g_psum2[4][C_DIM];

__device__ __forceinline__ unsigned f2tf32(float x) {
    unsigned y;
    asm("cvt.rna.tf32.f32 %0, %1;" : "=r"(y) : "f"(x));
    return y;
}

__device__ __forceinline__ void mma_tf32(float c[4], unsigned a0, unsigned a1,
                                         unsigned a2, unsigned a3,
                                         unsigned b0, unsigned b1) {
    asm volatile(
        "mma.sync.aligned.m16n8k8.row.col.f32.tf32.tf32.f32 "
        "{%0,%1,%2,%3}, {%4,%5,%6,%7}, {%8,%9}, {%0,%1,%2,%3};\n"
        : "+f"(c[0]), "+f"(c[1]), "+f"(c[2]), "+f"(c[3])
        : "r"(a0), "r"(a1), "r"(a2), "r"(a3), "r"(b0), "r"(b1));
}

// ---------------------------------------------------------------------------
// K1: projection GEMMs on tensor cores (TF32).
// P_z[8192, 50] = A_z[8192, 4096] @ W_z[4096, 50]
// BM=128, BK=32, N padded to 64. 256 threads = 8 warps in 4(M) x 2(N).
// Each warp: 32 rows x 32 cols = 2 m16-tiles x 4 n8-tiles.
// Smem strides chosen so bank = (4*row + k) mod 32 -> conflict-free frags.
// ---------------------------------------------------------------------------
__global__ __launch_bounds__(256) void k_proj_tc(
    const float* __restrict__ q, const float* __restrict__ k,
    const float* __restrict__ v,
    const float* __restrict__ wq, const float* __restrict__ wk,
    const float* __restrict__ wv)
{
    const int z = blockIdx.z;
    const float* __restrict__ A = (z == 0) ? q : (z == 1) ? k : v;
    const float* __restrict__ W = (z == 0) ? wq : (z == 1) ? wk : wv;
    float* __restrict__ P = g_P[z];

    __shared__ unsigned As[128][36];   // [m][k], stride 36: 4m+k banks
    __shared__ unsigned Ws[64][36];    // [n][k]

    const int tid  = threadIdx.x;
    const int warp = tid >> 5;
    const int lane = tid & 31;
    const int g = lane >> 2;       // 0..7
    const int t = lane & 3;        // 0..3
    const int wm = (warp & 3) * 32;
    const int wn = (warp >> 2) * 32;
    const int m0 = blockIdx.x * 128;

    float acc[2][4][4];
#pragma unroll
    for (int mi = 0; mi < 2; mi++)
#pragma unroll
        for (int ni = 0; ni < 4; ni++)
#pragma unroll
            for (int r = 0; r < 4; r++) acc[mi][ni][r] = 0.f;

    const int wn_col = tid & 63;       // W load: n index
    const int wk_row = tid >> 6;       // W load: k base (0..3)

    for (int k0 = 0; k0 < HW; k0 += 32) {
        // A tile: 128x32 floats = 1024 float4, 4 per thread
#pragma unroll
        for (int j = 0; j < 4; j++) {
            int i   = tid + j * 256;
            int row = i >> 3;
            int c4  = (i & 7) * 4;
            float4 a4 = *(const float4*)&A[(size_t)(m0 + row) * HW + k0 + c4];
            uint4 u;
            u.x = f2tf32(a4.x); u.y = f2tf32(a4.y);
            u.z = f2tf32(a4.z); u.w = f2tf32(a4.w);
            *(uint4*)&As[row][c4] = u;   // row*144B + 16*c4 -> 16B aligned
        }
        // W tile: 32x64 (n-padded), transposed into [n][k]
#pragma unroll
        for (int j = 0; j < 8; j++) {
            int kk = wk_row + j * 4;
            float val = (wn_col < PROJ) ? W[(k0 + kk) * PROJ + wn_col] : 0.f;
            Ws[wn_col][kk] = f2tf32(val);
        }
        __syncthreads();

#pragma unroll
        for (int ks = 0; ks < 4; ks++) {
            const int kb = ks * 8;
            unsigned af[2][4];
#pragma unroll
            for (int mi = 0; mi < 2; mi++) {
                int row = wm + mi * 16;
                af[mi][0] = As[row + g][kb + t];
                af[mi][1] = As[row + g + 8][kb + t];
                af[mi][2] = As[row + g][kb + t + 4];
                af[mi][3] = As[row + g + 8][kb + t + 4];
            }
#pragma unroll
            for (int ni = 0; ni < 4; ni++) {
                int ncol = wn + ni * 8 + g;
                unsigned b0 = Ws[ncol][kb + t];
                unsigned b1 = Ws[ncol][kb + t + 4];
                mma_tf32(acc[0][ni], af[0][0], af[0][1], af[0][2], af[0][3], b0, b1);
                mma_tf32(acc[1][ni], af[1][0], af[1][1], af[1][2], af[1][3], b0, b1);
            }
        }
        __syncthreads();
    }

    // Epilogue: c0,c1 -> (row g, cols 2t,2t+1); c2,c3 -> row g+8
#pragma unroll
    for (int mi = 0; mi < 2; mi++) {
#pragma unroll
        for (int ni = 0; ni < 4; ni++) {
            int row = m0 + wm + mi * 16 + g;
            int col = wn + ni * 8 + 2 * t;
            if (col < PROJ) {
                P[row * PROJ + col]           = acc[mi][ni][0];
                P[row * PROJ + col + 1]       = acc[mi][ni][1];
                P[(row + 8) * PROJ + col]     = acc[mi][ni][2];
                P[(row + 8) * PROJ + col + 1] = acc[mi][ni][3];
            }
        }
    }
}

// ---------------------------------------------------------------------------
// K2: attention (tiny). One block per batch, one thread per channel.
// ---------------------------------------------------------------------------
__global__ __launch_bounds__(256) void k_attn()
{
    const int b = blockIdx.x;
    const int c = threadIdx.x;
    const int lane = c & 31;
    const int wid  = c >> 5;

    const float* __restrict__ pq = &g_P[0][(b * C_DIM + c) * PROJ];
    const float* __restrict__ pk = &g_P[1][(b * C_DIM + c) * PROJ];
    const float* __restrict__ pv = &g_P[2][(b * C_DIM + c) * PROJ];

    float s[NH * NH];
#pragma unroll
    for (int i = 0; i < NH; i++)
#pragma unroll
        for (int j = 0; j < NH; j++) {
            float a = 0.f;
#pragma unroll
            for (int l = 0; l < LD; l++)
                a = fmaf(pq[i * LD + l], pk[j * LD + l], a);
            s[i * NH + j] = a;
        }

    __shared__ float sW[8][NH * NH];
    __shared__ float sA[NH * NH];

#pragma unroll
    for (int tt = 0; tt < NH * NH; tt++) {
        float x = s[tt];
#pragma unroll
        for (int off = 16; off > 0; off >>= 1)
            x += __shfl_down_sync(0xffffffffu, x, off);
        if (lane == 0) sW[wid][tt] = x;
    }
    __syncthreads();

    if (c < NH) {
        const int i = c;
        const float inv_scale = rsqrtf((float)(C_DIM * LD));
        float row[NH];
        float mx = -1e30f;
#pragma unroll
        for (int j = 0; j < NH; j++) {
            float a = 0.f;
#pragma unroll
            for (int w = 0; w < 8; w++) a += sW[w][i * NH + j];
            row[j] = a * inv_scale;
            mx = fmaxf(mx, row[j]);
        }
        float sum = 0.f;
#pragma unroll
        for (int j = 0; j < NH; j++) { row[j] = expf(row[j] - mx); sum += row[j]; }
        float inv = 1.f / sum;
#pragma unroll
        for (int j = 0; j < NH; j++) sA[i * NH + j] = row[j] * inv;
    }
    __syncthreads();

    float* __restrict__ va = &g_Va[(b * C_DIM + c) * PROJ];
#pragma unroll
    for (int n = 0; n < NH; n++)
#pragma unroll
        for (int l = 0; l < LD; l++) {
            float a = pv[n * LD + l];
#pragma unroll
            for (int j = 0; j < NH; j++)
                a = fmaf(sA[n * NH + j], pv[j * LD + l], a);
            va[n * LD + l] = a;
        }
}

// ---------------------------------------------------------------------------
// K3: output GEMM on tensor cores + residual.
// out[8192, 4096] = v + Va[8192,50] @ wfc[50,4096].  K padded 50->56.
// BM=128, BN=64, single K chunk. Same warp layout as k_proj_tc.
// Smem stride 60: bank = (-4*row + k) mod 32 -> conflict-free.
// ---------------------------------------------------------------------------
__global__ __launch_bounds__(256) void k_out_tc(
    const float* __restrict__ v, const float* __restrict__ wfc,
    float* __restrict__ out)
{
    __shared__ unsigned VaS[128][60];  // [m][k] k in 0..55
    __shared__ unsigned Ws[64][60];    // [n][k]

    const int tid  = threadIdx.x;
    const int warp = tid >> 5;
    const int lane = tid & 31;
    const int g = lane >> 2;
    const int t = lane & 3;
    const int wm = (warp & 3) * 32;
    const int wn = (warp >> 2) * 32;
    const int n0 = blockIdx.x * 64;
    const int m0 = blockIdx.y * 128;

    // Va tile 128 x 56 (cols >=50 zero)
    for (int i = tid; i < 128 * PROJ; i += 256) {
        int r = i / PROJ;
        int cc = i - r * PROJ;
        VaS[r][cc] = f2tf32(g_Va[(m0 + r) * PROJ + cc]);
    }
    for (int i = tid; i < 128 * 6; i += 256) {
        int r = i / 6;
        VaS[r][PROJ + (i - r * 6)] = 0u;
    }
    // wfc tile: [n][k], k >= 50 zero
    for (int i = tid; i < 64 * 56; i += 256) {
        int n  = i & 63;
        int kk = i >> 6;
        float val = (kk < PROJ) ? wfc[kk * HW + n0 + n] : 0.f;
        Ws[n][kk] = f2tf32(val);
    }
    __syncthreads();

    float acc[2][4][4];
#pragma unroll
    for (int mi = 0; mi < 2; mi++)
#pragma unroll
        for (int ni = 0; ni < 4; ni++)
#pragma unroll
            for (int r = 0; r < 4; r++) acc[mi][ni][r] = 0.f;

#pragma unroll
    for (int ks = 0; ks < 7; ks++) {
        const int kb = ks * 8;
        unsigned af[2][4];
#pragma unroll
        for (int mi = 0; mi < 2; mi++) {
            int row = wm + mi * 16;
            af[mi][0] = VaS[row + g][kb + t];
            af[mi][1] = VaS[row + g + 8][kb + t];
            af[mi][2] = VaS[row + g][kb + t + 4];
            af[mi][3] = VaS[row + g + 8][kb + t + 4];
        }
#pragma unroll
        for (int ni = 0; ni < 4; ni++) {
            int ncol = wn + ni * 8 + g;
            unsigned b0 = Ws[ncol][kb + t];
            unsigned b1 = Ws[ncol][kb + t + 4];
            mma_tf32(acc[0][ni], af[0][0], af[0][1], af[0][2], af[0][3], b0, b1);
            mma_tf32(acc[1][ni], af[1][0], af[1][1], af[1][2], af[1][3], b0, b1);
        }
    }

    // Epilogue: out = v + acc  (float2 stores, rows g and g+8 per tile)
#pragma unroll
    for (int mi = 0; mi < 2; mi++) {
#pragma unroll
        for (int ni = 0; ni < 4; ni++) {
            size_t base0 = (size_t)(m0 + wm + mi * 16 + g) * HW + n0 + wn + ni * 8 + 2 * t;
            size_t base1 = base0 + (size_t)8 * HW;
            float2 v0 = *(const float2*)&v[base0];
            float2 v1 = *(const float2*)&v[base1];
            float2 o0, o1;
            o0.x = v0.x + acc[mi][ni][0];
            o0.y = v0.y + acc[mi][ni][1];
            o1.x = v1.x + acc[mi][ni][2];
            o1.y = v1.y + acc[mi][ni][3];
            *(float2*)&out[base0] = o0;
            *(float2*)&out[base1] = o1;
        }
    }
}

// ---------------------------------------------------------------------------
// K4a: partial batch stats. grid = (256 channels, 4 batch-slices), 512 thr.
// ---------------------------------------------------------------------------
__global__ __launch_bounds__(512) void k_stats(const float* __restrict__ raw)
{
    const int c  = blockIdx.x;
    const int bs = blockIdx.y;          // 0..3, covers 8 batches each
    const int tid = threadIdx.x;
    float s = 0.f, s2 = 0.f;

    for (int b = bs * 8; b < bs * 8 + 8; b++) {
        const float4* __restrict__ p =
            (const float4*)&raw[((size_t)b * C_DIM + c) * HW];
#pragma unroll
        for (int it = 0; it < 2; it++) {
            float4 x = p[tid + it * 512];
            s  += x.x + x.y + x.z + x.w;
            s2 += x.x * x.x + x.y * x.y + x.z * x.z + x.w * x.w;
        }
    }

    __shared__ float rs[512], rs2[512];
    rs[tid] = s; rs2[tid] = s2;
    __syncthreads();
    for (int off = 256; off > 0; off >>= 1) {
        if (tid < off) { rs[tid] += rs[tid + off]; rs2[tid] += rs2[tid + off]; }
        __syncthreads();
    }
    if (tid == 0) {
        g_psum[bs][c]  = rs[0];
        g_psum2[bs][c] = rs2[0];
    }
}

// K4b: combine partials -> scale/shift
__global__ __launch_bounds__(256) void k_bnfinal(
    const float* __restrict__ gamma, const float* __restrict__ beta)
{
    const int c = threadIdx.x;
    float s = 0.f, s2 = 0.f;
#pragma unroll
    for (int j = 0; j < 4; j++) { s += g_psum[j][c]; s2 += g_psum2[j][c]; }
    const float inv_n = 1.f / (float)(B_DIM * HW);
    float mean = s * inv_n;
    float var  = s2 * inv_n - mean * mean;
    float sc = gamma[c] * rsqrtf(var + BN_EPS);
    g_scale[c] = sc;
    g_shift[c] = beta[c] - mean * sc;
}

// ---------------------------------------------------------------------------
// K5: apply BN affine in place.
// ---------------------------------------------------------------------------
__global__ __launch_bounds__(256) void k_apply(float* __restrict__ out)
{
    float4* __restrict__ p = (float4*)out;
    const int idx = blockIdx.x * 256 + threadIdx.x;
#pragma unroll
    for (int tt = 0; tt < 4; tt++) {
        int i = idx + tt * (8192 * 256);
        int c = (i >> 10) & 255;
        float sc = g_scale[c], sh = g_shift[c];
        float4 x = p[i];
        x.x = fmaf(x.x, sc, sh);
        x.y = fmaf(x.y, sc, sh);
        x.z = fmaf(x.z, sc, sh);
        x.w = fmaf(x.w, sc, sh);
        p[i] = x;
    }
}

// ---------------------------------------------------------------------------
extern "C" void kernel_launch(void* const* d_in, const int* in_sizes, int n_in,
                              void* d_out, int out_size)
{
    (void)in_sizes; (void)n_in; (void)out_size;
    const float* q     = (const float*)d_in[0];
    const float* k     = (const float*)d_in[1];
    const float* v     = (const float*)d_in[2];
    const float* wq    = (const float*)d_in[3];
    const float* wk    = (const float*)d_in[4];
    const float* wv    = (const float*)d_in[5];
    const float* wfc   = (const float*)d_in[6];
    const float* gamma = (const float*)d_in[7];
    const float* beta  = (const float*)d_in[8];
    float* out = (float*)d_out;

    k_proj_tc<<<dim3(M_ROWS / 128, 1, 3), 256>>>(q, k, v, wq, wk, wv);
    k_attn<<<B_DIM, 256>>>();
    k_out_tc<<<dim3(HW / 64, M_ROWS / 128), 256>>>(v, wfc, out);
    k_stats<<<dim3(C_DIM, 4), 512>>>(out);
    k_bnfinal<<<1, 256>>>(gamma, beta);
    k_apply<<<8192, 256>>>(out);
}

// round 5
// speedup vs baseline: 2.2406x; 1.3385x over previous
#include <cuda_runtime.h>

// Problem constants
#define NH    5
#define LD    10
#define PROJ  50           // NH*LD
#define C_DIM 256
#define B_DIM 32
#define HW    4096
#define M_ROWS (B_DIM * C_DIM)   // 8192
#define BN_EPS 1e-5f
#define KSPLIT 4
#define KSLICE (HW / KSPLIT)     // 1024

// Scratch (device globals: no allocations allowed)
__device__ float g_Pp[3][KSPLIT][M_ROWS * PROJ];  // split-K partials
__device__ float g_P[3][M_ROWS * PROJ];           // reduced projections
__device__ float g_Va[M_ROWS * PROJ];             // attention output
__device__ float g_osum[64][M_ROWS];              // per-(nblk,row) sum of out
__device__ float g_osq[64][M_ROWS];               // per-(nblk,row) sum of out^2
__device__ float g_scale[C_DIM];
__device__ float g_shift[C_DIM];

__device__ __forceinline__ unsigned f2tf32(float x) {
    unsigned y;
    asm("cvt.rna.tf32.f32 %0, %1;" : "=r"(y) : "f"(x));
    return y;
}

__device__ __forceinline__ void mma_tf32(float c[4], unsigned a0, unsigned a1,
                                         unsigned a2, unsigned a3,
                                         unsigned b0, unsigned b1) {
    asm volatile(
        "mma.sync.aligned.m16n8k8.row.col.f32.tf32.tf32.f32 "
        "{%0,%1,%2,%3}, {%4,%5,%6,%7}, {%8,%9}, {%0,%1,%2,%3};\n"
        : "+f"(c[0]), "+f"(c[1]), "+f"(c[2]), "+f"(c[3])
        : "r"(a0), "r"(a1), "r"(a2), "r"(a3), "r"(b0), "r"(b1));
}

__device__ __forceinline__ void cp_async16(unsigned smem_dst, const void* gsrc) {
    asm volatile("cp.async.cg.shared.global [%0], [%1], 16;\n"
                 :: "r"(smem_dst), "l"(gsrc));
}
__device__ __forceinline__ void cp_commit() {
    asm volatile("cp.async.commit_group;\n");
}
__device__ __forceinline__ void cp_wait0() {
    asm volatile("cp.async.wait_group 0;\n");
}

// ---------------------------------------------------------------------------
// K1: projection GEMMs, TF32 tensor cores, split-K x4, cp.async double buffer.
// P_z,slice[8192, 50] = A_z[8192, kslice] @ W_z[kslice, 50]
// BM=128, BK=32. 256 threads = 8 warps (4 M x 2 N). Warp: 32x32.
// A smem: [2][128][32] XOR-swizzled (col ^ 4*(row&7)) -> conflict-free.
// W smem: [2][32][64] k-major, XOR-swizzled (n ^ 8*(k&3)) -> conflict-free.
// Static smem = 32768 + 16384 = 49152 B (limit).
// ---------------------------------------------------------------------------
__global__ __launch_bounds__(256) void k_proj_tc(
    const float* __restrict__ q, const float* __restrict__ k,
    const float* __restrict__ v,
    const float* __restrict__ wq, const float* __restrict__ wk,
    const float* __restrict__ wv)
{
    const int z = blockIdx.z;
    const float* __restrict__ A = (z == 0) ? q : (z == 1) ? k : v;
    const float* __restrict__ W = (z == 0) ? wq : (z == 1) ? wk : wv;
    const int slice = blockIdx.y;
    float* __restrict__ P = g_Pp[z][slice];
    const int kbase = slice * KSLICE;

    __shared__ unsigned As[2][128][32];
    __shared__ unsigned Ws[2][32][64];

    const int tid  = threadIdx.x;
    const int warp = tid >> 5;
    const int lane = tid & 31;
    const int g = lane >> 2;
    const int t = lane & 3;
    const int wm = (warp & 3) * 32;
    const int wn = (warp >> 2) * 32;
    const int m0 = blockIdx.x * 128;

    const unsigned as_base = (unsigned)__cvta_generic_to_shared(&As[0][0][0]);

    // zero W buffers (pad n>=50 stays zero forever; valid n rewritten each tile)
    {
        unsigned* wsflat = &Ws[0][0][0];
#pragma unroll
        for (int i = 0; i < 16; i++) wsflat[tid + i * 256] = 0u;
    }
    __syncthreads();

    float acc[2][4][4];
#pragma unroll
    for (int mi = 0; mi < 2; mi++)
#pragma unroll
        for (int ni = 0; ni < 4; ni++)
#pragma unroll
            for (int r = 0; r < 4; r++) acc[mi][ni][r] = 0.f;

    const int wn_col = tid & 63;
    const int wk_row = tid >> 6;   // 0..3

    // ---- tile load helpers (as macros via lambdas) ----
    auto issue_A = [&](int buf, int k0) {
#pragma unroll
        for (int j = 0; j < 4; j++) {
            int i   = tid + j * 256;
            int row = i >> 3;
            int c4  = (i & 7) * 4;
            int sc  = c4 ^ (4 * (row & 7));            // XOR swizzle, 16B aligned
            unsigned dst = as_base + ((buf * 128 + row) * 32 + sc) * 4;
            cp_async16(dst, &A[(size_t)(m0 + row) * HW + k0 + c4]);
        }
        cp_commit();
    };
    auto load_W = [&](int buf, int k0) {
        if (wn_col < PROJ) {
#pragma unroll
            for (int j = 0; j < 8; j++) {
                int kk = wk_row + j * 4;
                Ws[buf][kk][wn_col ^ (8 * (kk & 3))] =
                    f2tf32(W[(k0 + kk) * PROJ + wn_col]);
            }
        }
    };

    const int NT = KSLICE / 32;   // 32 tiles
    issue_A(0, kbase);
    load_W(0, kbase);
    cp_wait0();
    __syncthreads();

    for (int kt = 0; kt < NT; kt++) {
        const int buf = kt & 1;
        if (kt + 1 < NT) {
            issue_A(buf ^ 1, kbase + (kt + 1) * 32);
            load_W(buf ^ 1, kbase + (kt + 1) * 32);
        }

#pragma unroll
        for (int ks = 0; ks < 4; ks++) {
            const int kb = ks * 8;
            unsigned af[2][4];
#pragma unroll
            for (int mi = 0; mi < 2; mi++) {
                int r0 = wm + mi * 16 + g;
                int sw = 4 * (g & 7);
                af[mi][0] = f2tf32(__uint_as_float(As[buf][r0][(kb + t) ^ sw]));
                af[mi][1] = f2tf32(__uint_as_float(As[buf][r0 + 8][(kb + t) ^ sw]));
                af[mi][2] = f2tf32(__uint_as_float(As[buf][r0][(kb + t + 4) ^ sw]));
                af[mi][3] = f2tf32(__uint_as_float(As[buf][r0 + 8][(kb + t + 4) ^ sw]));
            }
#pragma unroll
            for (int ni = 0; ni < 4; ni++) {
                int ncol = wn + ni * 8 + g;
                unsigned b0 = Ws[buf][kb + t][ncol ^ (8 * t)];
                unsigned b1 = Ws[buf][kb + t + 4][ncol ^ (8 * t)];
                mma_tf32(acc[0][ni], af[0][0], af[0][1], af[0][2], af[0][3], b0, b1);
                mma_tf32(acc[1][ni], af[1][0], af[1][1], af[1][2], af[1][3], b0, b1);
            }
        }

        if (kt + 1 < NT) cp_wait0();
        __syncthreads();
    }

#pragma unroll
    for (int mi = 0; mi < 2; mi++) {
#pragma unroll
        for (int ni = 0; ni < 4; ni++) {
            int row = m0 + wm + mi * 16 + g;
            int col = wn + ni * 8 + 2 * t;
            if (col < PROJ) {
                P[row * PROJ + col]           = acc[mi][ni][0];
                P[row * PROJ + col + 1]       = acc[mi][ni][1];
                P[(row + 8) * PROJ + col]     = acc[mi][ni][2];
                P[(row + 8) * PROJ + col + 1] = acc[mi][ni][3];
            }
        }
    }
}

// ---------------------------------------------------------------------------
// K1b: reduce split-K partials. 3*409600 floats / 4 = 307200 float4.
// ---------------------------------------------------------------------------
__global__ __launch_bounds__(256) void k_reduceP()
{
    const int i = blockIdx.x * 256 + threadIdx.x;       // 0..307199
    const int per_z = (M_ROWS * PROJ) / 4;              // 102400
    const int z = i / per_z;
    const int r = i - z * per_z;
    const float4* __restrict__ p = (const float4*)g_Pp;
    float4 a = p[(size_t)(z * KSPLIT + 0) * per_z + r];
    float4 b = p[(size_t)(z * KSPLIT + 1) * per_z + r];
    float4 c = p[(size_t)(z * KSPLIT + 2) * per_z + r];
    float4 d = p[(size_t)(z * KSPLIT + 3) * per_z + r];
    float4 o;
    o.x = (a.x + b.x) + (c.x + d.x);
    o.y = (a.y + b.y) + (c.y + d.y);
    o.z = (a.z + b.z) + (c.z + d.z);
    o.w = (a.w + b.w) + (c.w + d.w);
    ((float4*)g_P)[i] = o;
}

// ---------------------------------------------------------------------------
// K2: attention (tiny). One block per batch, one thread per channel.
// ---------------------------------------------------------------------------
__global__ __launch_bounds__(256) void k_attn()
{
    const int b = blockIdx.x;
    const int c = threadIdx.x;
    const int lane = c & 31;
    const int wid  = c >> 5;

    const float* __restrict__ pq = &g_P[0][(b * C_DIM + c) * PROJ];
    const float* __restrict__ pk = &g_P[1][(b * C_DIM + c) * PROJ];
    const float* __restrict__ pv = &g_P[2][(b * C_DIM + c) * PROJ];

    float s[NH * NH];
#pragma unroll
    for (int i = 0; i < NH; i++)
#pragma unroll
        for (int j = 0; j < NH; j++) {
            float a = 0.f;
#pragma unroll
            for (int l = 0; l < LD; l++)
                a = fmaf(pq[i * LD + l], pk[j * LD + l], a);
            s[i * NH + j] = a;
        }

    __shared__ float sW[8][NH * NH];
    __shared__ float sA[NH * NH];

#pragma unroll
    for (int tt = 0; tt < NH * NH; tt++) {
        float x = s[tt];
#pragma unroll
        for (int off = 16; off > 0; off >>= 1)
            x += __shfl_down_sync(0xffffffffu, x, off);
        if (lane == 0) sW[wid][tt] = x;
    }
    __syncthreads();

    if (c < NH) {
        const int i = c;
        const float inv_scale = rsqrtf((float)(C_DIM * LD));
        float row[NH];
        float mx = -1e30f;
#pragma unroll
        for (int j = 0; j < NH; j++) {
            float a = 0.f;
#pragma unroll
            for (int w = 0; w < 8; w++) a += sW[w][i * NH + j];
            row[j] = a * inv_scale;
            mx = fmaxf(mx, row[j]);
        }
        float sum = 0.f;
#pragma unroll
        for (int j = 0; j < NH; j++) { row[j] = expf(row[j] - mx); sum += row[j]; }
        float inv = 1.f / sum;
#pragma unroll
        for (int j = 0; j < NH; j++) sA[i * NH + j] = row[j] * inv;
    }
    __syncthreads();

    float* __restrict__ va = &g_Va[(b * C_DIM + c) * PROJ];
#pragma unroll
    for (int n = 0; n < NH; n++)
#pragma unroll
        for (int l = 0; l < LD; l++) {
            float a = pv[n * LD + l];
#pragma unroll
            for (int j = 0; j < NH; j++)
                a = fmaf(sA[n * NH + j], pv[j * LD + l], a);
            va[n * LD + l] = a;
        }
}

// ---------------------------------------------------------------------------
// K3: output GEMM + residual + fused per-row BN partial stats.
// out[8192, 4096] = v + Va[8192,50] @ wfc[50,4096].  K padded 50->56.
// BM=128, BN=64. Epilogue reduces sum/sumsq per row into g_osum/g_osq.
// ---------------------------------------------------------------------------
__global__ __launch_bounds__(256) void k_out_tc(
    const float* __restrict__ v, const float* __restrict__ wfc,
    float* __restrict__ out)
{
    __shared__ unsigned VaS[128][60];
    __shared__ unsigned Ws[64][60];
    __shared__ float Ssum[128][2];
    __shared__ float Ssq[128][2];

    const int tid  = threadIdx.x;
    const int warp = tid >> 5;
    const int lane = tid & 31;
    const int g = lane >> 2;
    const int t = lane & 3;
    const int wm = (warp & 3) * 32;
    const int wn = (warp >> 2) * 32;
    const int n0 = blockIdx.x * 64;
    const int m0 = blockIdx.y * 128;

    for (int i = tid; i < 128 * PROJ; i += 256) {
        int r = i / PROJ;
        int cc = i - r * PROJ;
        VaS[r][cc] = f2tf32(g_Va[(m0 + r) * PROJ + cc]);
    }
    for (int i = tid; i < 128 * 6; i += 256) {
        int r = i / 6;
        VaS[r][PROJ + (i - r * 6)] = 0u;
    }
    for (int i = tid; i < 64 * 56; i += 256) {
        int n  = i & 63;
        int kk = i >> 6;
        float val = (kk < PROJ) ? wfc[kk * HW + n0 + n] : 0.f;
        Ws[n][kk] = f2tf32(val);
    }
    __syncthreads();

    float acc[2][4][4];
#pragma unroll
    for (int mi = 0; mi < 2; mi++)
#pragma unroll
        for (int ni = 0; ni < 4; ni++)
#pragma unroll
            for (int r = 0; r < 4; r++) acc[mi][ni][r] = 0.f;

#pragma unroll
    for (int ks = 0; ks < 7; ks++) {
        const int kb = ks * 8;
        unsigned af[2][4];
#pragma unroll
        for (int mi = 0; mi < 2; mi++) {
            int row = wm + mi * 16;
            af[mi][0] = VaS[row + g][kb + t];
            af[mi][1] = VaS[row + g + 8][kb + t];
            af[mi][2] = VaS[row + g][kb + t + 4];
            af[mi][3] = VaS[row + g + 8][kb + t + 4];
        }
#pragma unroll
        for (int ni = 0; ni < 4; ni++) {
            int ncol = wn + ni * 8 + g;
            unsigned b0 = Ws[ncol][kb + t];
            unsigned b1 = Ws[ncol][kb + t + 4];
            mma_tf32(acc[0][ni], af[0][0], af[0][1], af[0][2], af[0][3], b0, b1);
            mma_tf32(acc[1][ni], af[1][0], af[1][1], af[1][2], af[1][3], b0, b1);
        }
    }

    // Epilogue: out = v + acc, accumulate per-row sum / sumsq
    float rs[2][2] = {{0.f, 0.f}, {0.f, 0.f}};
    float rq[2][2] = {{0.f, 0.f}, {0.f, 0.f}};
#pragma unroll
    for (int mi = 0; mi < 2; mi++) {
#pragma unroll
        for (int ni = 0; ni < 4; ni++) {
            size_t base0 = (size_t)(m0 + wm + mi * 16 + g) * HW + n0 + wn + ni * 8 + 2 * t;
            size_t base1 = base0 + (size_t)8 * HW;
            float2 v0 = *(const float2*)&v[base0];
            float2 v1 = *(const float2*)&v[base1];
            float2 o0, o1;
            o0.x = v0.x + acc[mi][ni][0];
            o0.y = v0.y + acc[mi][ni][1];
            o1.x = v1.x + acc[mi][ni][2];
            o1.y = v1.y + acc[mi][ni][3];
            *(float2*)&out[base0] = o0;
            *(float2*)&out[base1] = o1;
            rs[mi][0] += o0.x + o0.y;
            rq[mi][0] += o0.x * o0.x + o0.y * o0.y;
            rs[mi][1] += o1.x + o1.y;
            rq[mi][1] += o1.x * o1.x + o1.y * o1.y;
        }
    }
    // quad reduce over t (lanes 4g..4g+3)
#pragma unroll
    for (int mi = 0; mi < 2; mi++)
#pragma unroll
        for (int h = 0; h < 2; h++) {
            rs[mi][h] += __shfl_xor_sync(0xffffffffu, rs[mi][h], 1);
            rs[mi][h] += __shfl_xor_sync(0xffffffffu, rs[mi][h], 2);
            rq[mi][h] += __shfl_xor_sync(0xffffffffu, rq[mi][h], 1);
            rq[mi][h] += __shfl_xor_sync(0xffffffffu, rq[mi][h], 2);
        }
    if (t == 0) {
#pragma unroll
        for (int mi = 0; mi < 2; mi++)
#pragma unroll
            for (int h = 0; h < 2; h++) {
                int r = wm + mi * 16 + g + h * 8;
                Ssum[r][warp >> 2] = rs[mi][h];
                Ssq[r][warp >> 2]  = rq[mi][h];
            }
    }
    __syncthreads();
    if (tid < 128) {
        g_osum[blockIdx.x][m0 + tid] = Ssum[tid][0] + Ssum[tid][1];
        g_osq[blockIdx.x][m0 + tid]  = Ssq[tid][0] + Ssq[tid][1];
    }
}

// ---------------------------------------------------------------------------
// K4: combine per-block partials -> per-channel scale/shift. 256 blocks.
// ---------------------------------------------------------------------------
__global__ __launch_bounds__(256) void k_bnfinal(
    const float* __restrict__ gamma, const float* __restrict__ beta)
{
    const int c = blockIdx.x;
    const int tid = threadIdx.x;
    float s = 0.f, s2 = 0.f;
    for (int i = tid; i < B_DIM * 64; i += 256) {     // 2048 entries
        int b  = i >> 6;
        int nb = i & 63;
        int row = b * C_DIM + c;
        s  += g_osum[nb][row];
        s2 += g_osq[nb][row];
    }
    __shared__ float rs[256], rs2[256];
    rs[tid] = s; rs2[tid] = s2;
    __syncthreads();
    for (int off = 128; off > 0; off >>= 1) {
        if (tid < off) { rs[tid] += rs[tid + off]; rs2[tid] += rs2[tid + off]; }
        __syncthreads();
    }
    if (tid == 0) {
        const float inv_n = 1.f / (float)(B_DIM * HW);
        float mean = rs[0] * inv_n;
        float var  = rs2[0] * inv_n - mean * mean;
        float sc = gamma[c] * rsqrtf(var + BN_EPS);
        g_scale[c] = sc;
        g_shift[c] = beta[c] - mean * sc;
    }
}

// ---------------------------------------------------------------------------
// K5: apply BN affine in place.
// ---------------------------------------------------------------------------
__global__ __launch_bounds__(256) void k_apply(float* __restrict__ out)
{
    float4* __restrict__ p = (float4*)out;
    const int idx = blockIdx.x * 256 + threadIdx.x;
#pragma unroll
    for (int tt = 0; tt < 4; tt++) {
        int i = idx + tt * (8192 * 256);
        int c = (i >> 10) & 255;
        float sc = g_scale[c], sh = g_shift[c];
        float4 x = p[i];
        x.x = fmaf(x.x, sc, sh);
        x.y = fmaf(x.y, sc, sh);
        x.z = fmaf(x.z, sc, sh);
        x.w = fmaf(x.w, sc, sh);
        p[i] = x;
    }
}

// ---------------------------------------------------------------------------
extern "C" void kernel_launch(void* const* d_in, const int* in_sizes, int n_in,
                              void* d_out, int out_size)
{
    (void)in_sizes; (void)n_in; (void)out_size;
    const float* q     = (const float*)d_in[0];
    const float* k     = (const float*)d_in[1];
    const float* v     = (const float*)d_in[2];
    const float* wq    = (const float*)d_in[3];
    const float* wk    = (const float*)d_in[4];
    const float* wv    = (const float*)d_in[5];
    const float* wfc   = (const float*)d_in[6];
    const float* gamma = (const float*)d_in[7];
    const float* beta  = (const float*)d_in[8];
    float* out = (float*)d_out;

    k_proj_tc<<<dim3(M_ROWS / 128, KSPLIT, 3), 256>>>(q, k, v, wq, wk, wv);
    k_reduceP<<<(3 * M_ROWS * PROJ / 4) / 256, 256>>>();
    k_attn<<<B_DIM, 256>>>();
    k_out_tc<<<dim3(HW / 64, M_ROWS / 128), 256>>>(v, wfc, out);
    k_bnfinal<<<C_DIM, 256>>>(gamma, beta);
    k_apply<<<8192, 256>>>(out);
}